// round 10
// baseline (speedup 1.0000x reference)
#include <cuda_runtime.h>
#include <cuda_fp16.h>
#include <cstdint>
#include <cstddef>
#include <math.h>

#define NB  16
#define NLQ 1024
#define NLK 1024
#define NDK 256
#define NDV 256

__device__ float    g_ks[NB * NLK];
__device__ unsigned g_maxi[NB];                    // zero-init; atomicMax idempotent
__device__ float    g_es[NB * NLK];
__device__ float    g_inv[NB * NLQ];
__device__ unsigned g_bits[NB * NLQ * 32];         // permuted: word w bit 4i+c <-> k=i*128+w*4+c
__device__ __half   g_vt[(size_t)NB * NDV * NLK];

__device__ __forceinline__ unsigned enc_ord(float f) {
    int x = __float_as_int(f);
    return (x >= 0) ? ((unsigned)x | 0x80000000u) : ~(unsigned)x;
}
__device__ __forceinline__ float dec_ord(unsigned u) {
    int x = (u & 0x80000000u) ? (int)(u & 0x7fffffffu) : (int)~u;
    return __int_as_float(x);
}

// ---- k_s = key·w, per-batch max --------------------------------------------
__global__ void ks_kernel(const float* __restrict__ key, const float* __restrict__ w) {
    __shared__ float ws[NDK];
    __shared__ float bm[8];
    int t = threadIdx.x;
    ws[t] = w[t];
    __syncthreads();
    int warp = t >> 5, lane = t & 31;
    int row = blockIdx.x * 8 + warp;
    const float4* kp = (const float4*)(key + (size_t)row * NDK);
    const float4* wp = (const float4*)ws;
    float s = 0.f;
#pragma unroll
    for (int i = 0; i < 2; i++) {
        float4 a = kp[lane + 32 * i], b4 = wp[lane + 32 * i];
        s = fmaf(a.x, b4.x, s); s = fmaf(a.y, b4.y, s);
        s = fmaf(a.z, b4.z, s); s = fmaf(a.w, b4.w, s);
    }
#pragma unroll
    for (int o = 16; o; o >>= 1) s += __shfl_xor_sync(0xffffffffu, s, o);
    if (lane == 0) { g_ks[row] = s; bm[warp] = s; }
    __syncthreads();
    if (t == 0) {
        float m = bm[0];
#pragma unroll
        for (int i = 1; i < 8; i++) m = fmaxf(m, bm[i]);
        atomicMax(&g_maxi[(unsigned)blockIdx.x >> 7], enc_ord(m));
    }
}

// ---- es = exp(ks - mx + 64 ln2), fp32 --------------------------------------
__global__ void escale_kernel() {
    int b = blockIdx.x, t = threadIdx.x;
    float mx = dec_ord(g_maxi[b]);
    g_es[b * NLK + t] = expf(g_ks[b * NLK + t] - mx + 44.3614195558365f);
}

// ---- per-row masked max + bit-pack (coalesced, permuted layout) ------------
__global__ void rowmax_kernel(const int* __restrict__ mask) {
    int wid = threadIdx.x >> 5, lane = threadIdx.x & 31;
    int row = blockIdx.x * 8 + wid;
    int b = row >> 10;
    const int4*   mp = (const int4*)(mask + (size_t)row * NLK);
    const float4* ep = (const float4*)(g_es + b * NLK);
    float m = 0.f;
    unsigned w = 0;
#pragma unroll
    for (int i = 0; i < 8; i++) {
        int idx = i * 32 + lane;            // k = idx*4 (coalesced)
        int4 mm = mp[idx];
        float4 ee = ep[idx];
        if (mm.x) m = fmaxf(m, ee.x);
        if (mm.y) m = fmaxf(m, ee.y);
        if (mm.z) m = fmaxf(m, ee.z);
        if (mm.w) m = fmaxf(m, ee.w);
        unsigned nib = (unsigned)(mm.x & 1) | ((unsigned)(mm.y & 1) << 1)
                     | ((unsigned)(mm.z & 1) << 2) | ((unsigned)(mm.w & 1) << 3);
        w |= nib << (4 * i);
    }
    g_bits[row * 32 + lane] = w;
#pragma unroll
    for (int o = 16; o; o >>= 1) m = fmaxf(m, __shfl_xor_sync(0xffffffffu, m, o));
    if (lane == 0) g_inv[row] = 1.0f / m;
}

// ---- V^T fp16 transpose ----------------------------------------------------
__global__ void vt_kernel(const float* __restrict__ value) {
    __shared__ float tile[32][33];
    int b = blockIdx.z, k0 = blockIdx.y * 32, dv0 = blockIdx.x * 32;
    int t = threadIdx.x;
    int r = t >> 3, c4 = (t & 7) * 4;
    float4 v = *(const float4*)(value + ((size_t)(b * NLK + k0 + r)) * NDV + dv0 + c4);
    tile[r][c4 + 0] = v.x; tile[r][c4 + 1] = v.y;
    tile[r][c4 + 2] = v.z; tile[r][c4 + 3] = v.w;
    __syncthreads();
    __half2 h0 = __floats2half2_rn(tile[c4 + 0][r], tile[c4 + 1][r]);
    __half2 h1 = __floats2half2_rn(tile[c4 + 2][r], tile[c4 + 3][r]);
    uint2 o;
    o.x = *(unsigned*)&h0; o.y = *(unsigned*)&h1;
    *(uint2*)(g_vt + ((size_t)(b * NDV + dv0 + r)) * NLK + k0 + c4) = o;
}

// ---- fp16 GEMM: BM=64, 256 threads, 2 CTAs/SM ------------------------------
#define BM 64
#define BN 256
#define BK 32
#define STG 3
#define APITCH 80
#define BPITCH 80
#define A_STAGE (BM * APITCH)              // 5120
#define B_STAGE (BN * BPITCH)              // 20480
#define OFF_B   (STG * A_STAGE)            // 15360
#define OFF_ES  (OFF_B + STG * B_STAGE)    // 76800
#define OFF_D   (OFF_ES + 4096)            // 80896
#define SMEM_REQ (OFF_D + 1024)            // 81920  (x2 CTAs = 160 KB/SM)

__device__ __forceinline__ void ldsm4(uint32_t* r, uint32_t addr) {
    asm volatile("ldmatrix.sync.aligned.m8n8.x4.shared.b16 {%0,%1,%2,%3}, [%4];"
                 : "=r"(r[0]), "=r"(r[1]), "=r"(r[2]), "=r"(r[3]) : "r"(addr));
}

__global__ __launch_bounds__(256, 2)
void attn_gemm(float* __restrict__ out) {
    extern __shared__ char smem[];
    const uint32_t sm = (uint32_t)__cvta_generic_to_shared(smem);
    float* Dens = (float*)(smem + OFF_D);

    const int tid = threadIdx.x, lane = tid & 31, wid = tid >> 5;
    const int b = blockIdx.y, qbase = blockIdx.x * BM;
    const int warpN = wid;                 // 8 warps x 32 cols
    const int g = lane >> 2, t4 = lane & 3;

    {   // es table to smem (fp32, 4 KB)
        ((float4*)(smem + OFF_ES))[tid] = ((const float4*)(g_es + b * NLK))[tid];
    }
    __syncthreads();

    const int ar = tid & 63, aq = tid >> 6;        // row, k-eighth
    const int grow = b * NLQ + qbase + ar;
    const float inv = g_inv[grow];
    unsigned bwreg[8];
    {
        const uint2* bp = (const uint2*)(g_bits + (size_t)grow * 32);
#pragma unroll
        for (int j = 0; j < 4; j++) {
            uint2 v = bp[aq + 4 * j];              // words 2aq+8j, +1
            bwreg[2 * j] = v.x; bwreg[2 * j + 1] = v.y;
        }
    }
    // B loader: thread t owns row t (64B per chunk)
    const __half* vb0 = g_vt + ((size_t)(b * NDV + tid)) * NLK;
    const uint32_t bd0 = sm + OFF_B + (uint32_t)(tid * BPITCH);

    float c[4][4][4];
#pragma unroll
    for (int i = 0; i < 4; i++)
#pragma unroll
        for (int j = 0; j < 4; j++)
#pragma unroll
            for (int k = 0; k < 4; k++) c[i][j][k] = 0.f;
    float dacc = 0.f;

    auto cpB = [&](int t, int s) {
        uint32_t dst = bd0 + (uint32_t)(s * B_STAGE);
        const __half* src = vb0 + t * BK;
        asm volatile("cp.async.cg.shared.global [%0], [%1], 16;" :: "r"(dst),      "l"(src));
        asm volatile("cp.async.cg.shared.global [%0], [%1], 16;" :: "r"(dst + 16), "l"(src + 8));
        asm volatile("cp.async.cg.shared.global [%0], [%1], 16;" :: "r"(dst + 32), "l"(src + 16));
        asm volatile("cp.async.cg.shared.global [%0], [%1], 16;" :: "r"(dst + 48), "l"(src + 24));
        asm volatile("cp.async.commit_group;" ::: "memory");
    };
    auto stsA = [&](int t, int s) {
        const int j = t & 3, i4 = (t >> 2) * 4;
        unsigned u = ((bwreg[2 * j] >> i4) & 0xFu) | (((bwreg[2 * j + 1] >> i4) & 0xFu) << 4);
        float4 e0, e1;
        uint32_t ea = sm + OFF_ES + (uint32_t)(t * 128 + aq * 32);
        asm volatile("ld.shared.v4.f32 {%0,%1,%2,%3}, [%4];"
                     : "=f"(e0.x), "=f"(e0.y), "=f"(e0.z), "=f"(e0.w) : "r"(ea));
        asm volatile("ld.shared.v4.f32 {%0,%1,%2,%3}, [%4];"
                     : "=f"(e1.x), "=f"(e1.y), "=f"(e1.z), "=f"(e1.w) : "r"(ea + 16));
        float a0 = (u & 1u)   ? e0.x * inv : 0.f;
        float a1 = (u & 2u)   ? e0.y * inv : 0.f;
        float a2 = (u & 4u)   ? e0.z * inv : 0.f;
        float a3 = (u & 8u)   ? e0.w * inv : 0.f;
        float a4 = (u & 16u)  ? e1.x * inv : 0.f;
        float a5 = (u & 32u)  ? e1.y * inv : 0.f;
        float a6 = (u & 64u)  ? e1.z * inv : 0.f;
        float a7 = (u & 128u) ? e1.w * inv : 0.f;
        __half2 h0 = __floats2half2_rn(a0, a1);
        __half2 h1 = __floats2half2_rn(a2, a3);
        __half2 h2 = __floats2half2_rn(a4, a5);
        __half2 h3 = __floats2half2_rn(a6, a7);
        float2 f0 = __half22float2(h0), f1 = __half22float2(h1);
        float2 f2 = __half22float2(h2), f3 = __half22float2(h3);
        dacc += (f0.x + f0.y) + (f1.x + f1.y) + (f2.x + f2.y) + (f3.x + f3.y);
        asm volatile("st.shared.v4.b32 [%0], {%1,%2,%3,%4};"
                     :: "r"(sm + (uint32_t)(s * A_STAGE + ar * APITCH + aq * 16)),
                        "r"(*(unsigned*)&h0), "r"(*(unsigned*)&h1),
                        "r"(*(unsigned*)&h2), "r"(*(unsigned*)&h3));
    };
    auto compute = [&](int s) {
        const uint32_t Ab = sm + (uint32_t)(s * A_STAGE);
        const uint32_t Bb = sm + OFF_B + (uint32_t)(s * B_STAGE);
        const uint32_t aad = Ab + (uint32_t)((lane & 15) * APITCH + (lane >> 4) * 16);
        const uint32_t bad = Bb + (uint32_t)((warpN * 32 + (lane & 7) + (lane >> 4) * 8) * BPITCH
                                             + ((lane >> 3) & 1) * 16);
#pragma unroll
        for (int k16 = 0; k16 < 2; k16++) {
            uint32_t a[4][4], bq[2][4];
#pragma unroll
            for (int mt = 0; mt < 4; mt++)
                ldsm4(a[mt], aad + (uint32_t)(mt * 16 * APITCH + k16 * 32));
#pragma unroll
            for (int np = 0; np < 2; np++)
                ldsm4(bq[np], bad + (uint32_t)(np * 16 * BPITCH + k16 * 32));
#pragma unroll
            for (int mt = 0; mt < 4; mt++)
#pragma unroll
                for (int nt = 0; nt < 4; nt++) {
                    const uint32_t b0 = bq[nt >> 1][(nt & 1) * 2];
                    const uint32_t b1 = bq[nt >> 1][(nt & 1) * 2 + 1];
                    asm volatile(
                        "mma.sync.aligned.m16n8k16.row.col.f32.f16.f16.f32 "
                        "{%0,%1,%2,%3}, {%4,%5,%6,%7}, {%8,%9}, {%0,%1,%2,%3};"
                        : "+f"(c[mt][nt][0]), "+f"(c[mt][nt][1]),
                          "+f"(c[mt][nt][2]), "+f"(c[mt][nt][3])
                        : "r"(a[mt][0]), "r"(a[mt][1]), "r"(a[mt][2]), "r"(a[mt][3]),
                          "r"(b0), "r"(b1));
                }
        }
    };

    // ---- 3-stage pipeline ----
    cpB(0, 0);
    cpB(1, 1);
    const int NKT = NLK / BK;   // 32
    for (int t = 0; t < NKT; t++) {
        int cs = t % 3;
        stsA(t, cs);
        if (t + 1 < NKT) asm volatile("cp.async.wait_group 1;" ::: "memory");
        else             asm volatile("cp.async.wait_group 0;" ::: "memory");
        __syncthreads();
        if (t + 2 < NKT) cpB(t + 2, (t + 2) % 3);
        compute(cs);
    }

    // ---- denominators & epilogue ----
    Dens[ar * 4 + aq] = dacc;
    __syncthreads();
#pragma unroll
    for (int mt = 0; mt < 4; mt++) {
        const int row = mt * 16 + g;
        float4 d0 = *(const float4*)(Dens + row * 4);
        float4 d1 = *(const float4*)(Dens + (row + 8) * 4);
        float inv0 = 1.0f / (d0.x + d0.y + d0.z + d0.w);
        float inv8 = 1.0f / (d1.x + d1.y + d1.z + d1.w);
        float* o0 = out + ((size_t)(b * NLQ + qbase + row)) * NDV;
#pragma unroll
        for (int nt = 0; nt < 4; nt++) {
            const int col = warpN * 32 + nt * 8 + 2 * t4;
            *(float2*)(o0 + col) =
                make_float2(c[mt][nt][0] * inv0, c[mt][nt][1] * inv0);
            *(float2*)(o0 + 8 * NDV + col) =
                make_float2(c[mt][nt][2] * inv8, c[mt][nt][3] * inv8);
        }
    }
}

// ---------------- launcher --------------------------------------------------
extern "C" void kernel_launch(void* const* d_in, const int* in_sizes, int n_in,
                              void* d_out, int out_size) {
    const float* key   = (const float*)d_in[1];
    const float* value = (const float*)d_in[2];
    const float* w     = (const float*)d_in[3];
    const int*   mask  = (const int*)d_in[4];
    float*       out   = (float*)d_out;

    cudaFuncSetAttribute(attn_gemm,
                         cudaFuncAttributeMaxDynamicSharedMemorySize, SMEM_REQ);

    ks_kernel<<<NB * NLK / 8, 256>>>(key, w);
    escale_kernel<<<NB, 1024>>>();
    rowmax_kernel<<<NB * NLQ / 8, 256>>>(mask);
    dim3 vg(NDV / 32, NLK / 32, NB);
    vt_kernel<<<vg, 256>>>(value);
    dim3 grid(NLQ / BM, NB);
    attn_gemm<<<grid, 256, SMEM_REQ>>>(out);
}

// round 12
// speedup vs baseline: 1.2183x; 1.2183x over previous
#include <cuda_runtime.h>
#include <cuda_fp16.h>
#include <cstdint>
#include <cstddef>
#include <math.h>

#define NB  16
#define NLQ 1024
#define NLK 1024
#define NDK 256
#define NDV 256

__device__ float    g_ks[NB * NLK];
__device__ unsigned g_maxi[NB];                    // zero-init; atomicMax idempotent
__device__ float    g_es[NB * NLK];
__device__ float    g_inv[NB * NLQ];
__device__ unsigned g_bits[NB * NLQ * 32];         // permuted: word w bit 4i+c <-> k=i*128+w*4+c
__device__ __half   g_vt[(size_t)NB * NDV * NLK];

__device__ __forceinline__ unsigned enc_ord(float f) {
    int x = __float_as_int(f);
    return (x >= 0) ? ((unsigned)x | 0x80000000u) : ~(unsigned)x;
}
__device__ __forceinline__ float dec_ord(unsigned u) {
    int x = (u & 0x80000000u) ? (int)(u & 0x7fffffffu) : (int)~u;
    return __int_as_float(x);
}

// ---- k_s = key·w, per-batch max --------------------------------------------
__global__ void ks_kernel(const float* __restrict__ key, const float* __restrict__ w) {
    __shared__ float ws[NDK];
    __shared__ float bm[8];
    int t = threadIdx.x;
    ws[t] = w[t];
    __syncthreads();
    int warp = t >> 5, lane = t & 31;
    int row = blockIdx.x * 8 + warp;
    const float4* kp = (const float4*)(key + (size_t)row * NDK);
    const float4* wp = (const float4*)ws;
    float s = 0.f;
#pragma unroll
    for (int i = 0; i < 2; i++) {
        float4 a = kp[lane + 32 * i], b4 = wp[lane + 32 * i];
        s = fmaf(a.x, b4.x, s); s = fmaf(a.y, b4.y, s);
        s = fmaf(a.z, b4.z, s); s = fmaf(a.w, b4.w, s);
    }
#pragma unroll
    for (int o = 16; o; o >>= 1) s += __shfl_xor_sync(0xffffffffu, s, o);
    if (lane == 0) { g_ks[row] = s; bm[warp] = s; }
    __syncthreads();
    if (t == 0) {
        float m = bm[0];
#pragma unroll
        for (int i = 1; i < 8; i++) m = fmaxf(m, bm[i]);
        atomicMax(&g_maxi[(unsigned)blockIdx.x >> 7], enc_ord(m));
    }
}

// ---- es = exp(ks - mx + 64 ln2), fp32 --------------------------------------
__global__ void escale_kernel() {
    int b = blockIdx.x, t = threadIdx.x;
    float mx = dec_ord(g_maxi[b]);
    g_es[b * NLK + t] = expf(g_ks[b * NLK + t] - mx + 44.3614195558365f);
}

// ---- per-row masked max + bit-pack (coalesced, permuted layout) ------------
__global__ void rowmax_kernel(const int* __restrict__ mask) {
    int wid = threadIdx.x >> 5, lane = threadIdx.x & 31;
    int row = blockIdx.x * 8 + wid;
    int b = row >> 10;
    const int4*   mp = (const int4*)(mask + (size_t)row * NLK);
    const float4* ep = (const float4*)(g_es + b * NLK);
    float m = 0.f;
    unsigned w = 0;
#pragma unroll
    for (int i = 0; i < 8; i++) {
        int idx = i * 32 + lane;
        int4 mm = mp[idx];
        float4 ee = ep[idx];
        if (mm.x) m = fmaxf(m, ee.x);
        if (mm.y) m = fmaxf(m, ee.y);
        if (mm.z) m = fmaxf(m, ee.z);
        if (mm.w) m = fmaxf(m, ee.w);
        unsigned nib = (unsigned)(mm.x & 1) | ((unsigned)(mm.y & 1) << 1)
                     | ((unsigned)(mm.z & 1) << 2) | ((unsigned)(mm.w & 1) << 3);
        w |= nib << (4 * i);
    }
    g_bits[row * 32 + lane] = w;
#pragma unroll
    for (int o = 16; o; o >>= 1) m = fmaxf(m, __shfl_xor_sync(0xffffffffu, m, o));
    if (lane == 0) g_inv[row] = 1.0f / m;
}

// ---- V^T fp16 transpose ----------------------------------------------------
__global__ void vt_kernel(const float* __restrict__ value) {
    __shared__ float tile[32][33];
    int b = blockIdx.z, k0 = blockIdx.y * 32, dv0 = blockIdx.x * 32;
    int t = threadIdx.x;
    int r = t >> 3, c4 = (t & 7) * 4;
    float4 v = *(const float4*)(value + ((size_t)(b * NLK + k0 + r)) * NDV + dv0 + c4);
    tile[r][c4 + 0] = v.x; tile[r][c4 + 1] = v.y;
    tile[r][c4 + 2] = v.z; tile[r][c4 + 3] = v.w;
    __syncthreads();
    __half2 h0 = __floats2half2_rn(tile[c4 + 0][r], tile[c4 + 1][r]);
    __half2 h1 = __floats2half2_rn(tile[c4 + 2][r], tile[c4 + 3][r]);
    uint2 o;
    o.x = *(unsigned*)&h0; o.y = *(unsigned*)&h1;
    *(uint2*)(g_vt + ((size_t)(b * NDV + dv0 + r)) * NLK + k0 + c4) = o;
}

// ---- fp16 GEMM: BM=128 x BN=128, 256 threads, 2 CTAs/SM --------------------
#define BM 128
#define BN 128
#define BK 32
#define STG 3
#define APITCH 80
#define BPITCH 80
#define A_STAGE (BM * APITCH)              // 10240
#define B_STAGE (BN * BPITCH)              // 10240
#define OFF_B   (STG * A_STAGE)            // 30720
#define OFF_ES  (OFF_B + STG * B_STAGE)    // 61440
#define OFF_D   (OFF_ES + 4096)            // 65536
#define SMEM_REQ (OFF_D + 1024)            // 66560  (x2 CTAs = 133 KB/SM)

__device__ __forceinline__ void ldsm4(uint32_t* r, uint32_t addr) {
    asm volatile("ldmatrix.sync.aligned.m8n8.x4.shared.b16 {%0,%1,%2,%3}, [%4];"
                 : "=r"(r[0]), "=r"(r[1]), "=r"(r[2]), "=r"(r[3]) : "r"(addr));
}

__global__ __launch_bounds__(256, 2)
void attn_gemm(float* __restrict__ out) {
    extern __shared__ char smem[];
    const uint32_t sm = (uint32_t)__cvta_generic_to_shared(smem);
    float* Dens = (float*)(smem + OFF_D);

    const int tid = threadIdx.x, lane = tid & 31, wid = tid >> 5;
    const int b = blockIdx.z, qbase = blockIdx.x * BM, nbase = blockIdx.y * BN;
    const int warpM = wid >> 2, warpN = wid & 3;   // 2 x 4 warps, tile 64x32
    const int g = lane >> 2, t4 = lane & 3;

    {   // es table to smem (fp32, 4 KB)
        ((float4*)(smem + OFF_ES))[tid] = ((const float4*)(g_es + b * NLK))[tid];
    }
    __syncthreads();

    const int ar = tid & 127, aq = tid >> 7;       // row, k-half (16 k each)
    const int grow = b * NLQ + qbase + ar;
    const float inv = g_inv[grow];
    uint4 bwreg[4];                                // words j*8+4aq .. +3 for j=0..3
    {
        const uint4* bp = (const uint4*)(g_bits + (size_t)grow * 32);
#pragma unroll
        for (int j = 0; j < 4; j++) bwreg[j] = bp[2 * j + aq];
    }
    // B loader: 2 threads per row, 32B each
    const int brow_ = tid >> 1, bco = (tid & 1) * 16;  // halfs offset
    const __half* vb0 = g_vt + ((size_t)(b * NDV + nbase + brow_)) * NLK + bco;
    const uint32_t bd0 = sm + OFF_B + (uint32_t)(brow_ * BPITCH + bco * 2);

    float c[4][4][4];
#pragma unroll
    for (int i = 0; i < 4; i++)
#pragma unroll
        for (int j = 0; j < 4; j++)
#pragma unroll
            for (int k = 0; k < 4; k++) c[i][j][k] = 0.f;
    float dacc = 0.f;

    auto cpB = [&](int t, int s) {
        uint32_t dst = bd0 + (uint32_t)(s * B_STAGE);
        const __half* src = vb0 + t * BK;
        asm volatile("cp.async.cg.shared.global [%0], [%1], 16;" :: "r"(dst),      "l"(src));
        asm volatile("cp.async.cg.shared.global [%0], [%1], 16;" :: "r"(dst + 16), "l"(src + 8));
        asm volatile("cp.async.commit_group;" ::: "memory");
    };
    auto stsA = [&](int t, int s) {
        const int j = t & 3, i4 = (t >> 2) * 4;
        uint4 wv = bwreg[j];
        unsigned n0 = (wv.x >> i4) & 0xFu, n1 = (wv.y >> i4) & 0xFu;
        unsigned n2 = (wv.z >> i4) & 0xFu, n3 = (wv.w >> i4) & 0xFu;
        float4 e0, e1, e2, e3;
        uint32_t ea = sm + OFF_ES + (uint32_t)(t * 128 + aq * 64);
        asm volatile("ld.shared.v4.f32 {%0,%1,%2,%3}, [%4];"
                     : "=f"(e0.x), "=f"(e0.y), "=f"(e0.z), "=f"(e0.w) : "r"(ea));
        asm volatile("ld.shared.v4.f32 {%0,%1,%2,%3}, [%4];"
                     : "=f"(e1.x), "=f"(e1.y), "=f"(e1.z), "=f"(e1.w) : "r"(ea + 16));
        asm volatile("ld.shared.v4.f32 {%0,%1,%2,%3}, [%4];"
                     : "=f"(e2.x), "=f"(e2.y), "=f"(e2.z), "=f"(e2.w) : "r"(ea + 32));
        asm volatile("ld.shared.v4.f32 {%0,%1,%2,%3}, [%4];"
                     : "=f"(e3.x), "=f"(e3.y), "=f"(e3.z), "=f"(e3.w) : "r"(ea + 48));
        float a0 = (n0 & 1u) ? e0.x * inv : 0.f, a1 = (n0 & 2u) ? e0.y * inv : 0.f;
        float a2 = (n0 & 4u) ? e0.z * inv : 0.f, a3 = (n0 & 8u) ? e0.w * inv : 0.f;
        float a4 = (n1 & 1u) ? e1.x * inv : 0.f, a5 = (n1 & 2u) ? e1.y * inv : 0.f;
        float a6 = (n1 & 4u) ? e1.z * inv : 0.f, a7 = (n1 & 8u) ? e1.w * inv : 0.f;
        float a8 = (n2 & 1u) ? e2.x * inv : 0.f, a9 = (n2 & 2u) ? e2.y * inv : 0.f;
        float aa = (n2 & 4u) ? e2.z * inv : 0.f, ab = (n2 & 8u) ? e2.w * inv : 0.f;
        float ac = (n3 & 1u) ? e3.x * inv : 0.f, ad = (n3 & 2u) ? e3.y * inv : 0.f;
        float ae = (n3 & 4u) ? e3.z * inv : 0.f, af = (n3 & 8u) ? e3.w * inv : 0.f;
        __half2 h0 = __floats2half2_rn(a0, a1), h1 = __floats2half2_rn(a2, a3);
        __half2 h2 = __floats2half2_rn(a4, a5), h3 = __floats2half2_rn(a6, a7);
        __half2 h4 = __floats2half2_rn(a8, a9), h5 = __floats2half2_rn(aa, ab);
        __half2 h6 = __floats2half2_rn(ac, ad), h7 = __floats2half2_rn(ae, af);
        float2 f;
        f = __half22float2(h0); dacc += f.x + f.y;
        f = __half22float2(h1); dacc += f.x + f.y;
        f = __half22float2(h2); dacc += f.x + f.y;
        f = __half22float2(h3); dacc += f.x + f.y;
        f = __half22float2(h4); dacc += f.x + f.y;
        f = __half22float2(h5); dacc += f.x + f.y;
        f = __half22float2(h6); dacc += f.x + f.y;
        f = __half22float2(h7); dacc += f.x + f.y;
        uint32_t sa = sm + (uint32_t)(s * A_STAGE + ar * APITCH + aq * 32);
        asm volatile("st.shared.v4.b32 [%0], {%1,%2,%3,%4};"
                     :: "r"(sa),
                        "r"(*(unsigned*)&h0), "r"(*(unsigned*)&h1),
                        "r"(*(unsigned*)&h2), "r"(*(unsigned*)&h3));
        asm volatile("st.shared.v4.b32 [%0], {%1,%2,%3,%4};"
                     :: "r"(sa + 16),
                        "r"(*(unsigned*)&h4), "r"(*(unsigned*)&h5),
                        "r"(*(unsigned*)&h6), "r"(*(unsigned*)&h7));
    };
    auto compute = [&](int s) {
        const uint32_t Ab = sm + (uint32_t)(s * A_STAGE);
        const uint32_t Bb = sm + OFF_B + (uint32_t)(s * B_STAGE);
        const uint32_t aad = Ab + (uint32_t)((warpM * 64 + (lane & 15)) * APITCH
                                             + (lane >> 4) * 16);
        const uint32_t bad = Bb + (uint32_t)((warpN * 32 + (lane & 7) + (lane >> 4) * 8) * BPITCH
                                             + ((lane >> 3) & 1) * 16);
#pragma unroll
        for (int k16 = 0; k16 < 2; k16++) {
            uint32_t a[4][4], bq[2][4];
#pragma unroll
            for (int mt = 0; mt < 4; mt++)
                ldsm4(a[mt], aad + (uint32_t)(mt * 16 * APITCH + k16 * 32));
#pragma unroll
            for (int np = 0; np < 2; np++)
                ldsm4(bq[np], bad + (uint32_t)(np * 16 * BPITCH + k16 * 32));
#pragma unroll
            for (int mt = 0; mt < 4; mt++)
#pragma unroll
                for (int nt = 0; nt < 4; nt++) {
                    const uint32_t b0 = bq[nt >> 1][(nt & 1) * 2];
                    const uint32_t b1 = bq[nt >> 1][(nt & 1) * 2 + 1];
                    asm volatile(
                        "mma.sync.aligned.m16n8k16.row.col.f32.f16.f16.f32 "
                        "{%0,%1,%2,%3}, {%4,%5,%6,%7}, {%8,%9}, {%0,%1,%2,%3};"
                        : "+f"(c[mt][nt][0]), "+f"(c[mt][nt][1]),
                          "+f"(c[mt][nt][2]), "+f"(c[mt][nt][3])
                        : "r"(a[mt][0]), "r"(a[mt][1]), "r"(a[mt][2]), "r"(a[mt][3]),
                          "r"(b0), "r"(b1));
                }
        }
    };

    // ---- 3-stage pipeline ----
    cpB(0, 0);
    cpB(1, 1);
    const int NKT = NLK / BK;   // 32
    for (int t = 0; t < NKT; t++) {
        int cs = t % 3;
        stsA(t, cs);
        if (t + 1 < NKT) asm volatile("cp.async.wait_group 1;" ::: "memory");
        else             asm volatile("cp.async.wait_group 0;" ::: "memory");
        __syncthreads();
        if (t + 2 < NKT) cpB(t + 2, (t + 2) % 3);
        compute(cs);
    }

    // ---- denominators & epilogue ----
    Dens[ar * 2 + aq] = dacc;
    __syncthreads();
#pragma unroll
    for (int mt = 0; mt < 4; mt++) {
        const int row = warpM * 64 + mt * 16 + g;
        float2 d0 = *(const float2*)(Dens + row * 2);
        float2 d1 = *(const float2*)(Dens + (row + 8) * 2);
        float inv0 = 1.0f / (d0.x + d0.y);
        float inv8 = 1.0f / (d1.x + d1.y);
        float* o0 = out + ((size_t)(b * NLQ + qbase + row)) * NDV + nbase;
#pragma unroll
        for (int nt = 0; nt < 4; nt++) {
            const int col = warpN * 32 + nt * 8 + 2 * t4;
            *(float2*)(o0 + col) =
                make_float2(c[mt][nt][0] * inv0, c[mt][nt][1] * inv0);
            *(float2*)(o0 + 8 * NDV + col) =
                make_float2(c[mt][nt][2] * inv8, c[mt][nt][3] * inv8);
        }
    }
}

// ---------------- launcher --------------------------------------------------
extern "C" void kernel_launch(void* const* d_in, const int* in_sizes, int n_in,
                              void* d_out, int out_size) {
    const float* key   = (const float*)d_in[1];
    const float* value = (const float*)d_in[2];
    const float* w     = (const float*)d_in[3];
    const int*   mask  = (const int*)d_in[4];
    float*       out   = (float*)d_out;

    cudaFuncSetAttribute(attn_gemm,
                         cudaFuncAttributeMaxDynamicSharedMemorySize, SMEM_REQ);

    ks_kernel<<<NB * NLK / 8, 256>>>(key, w);
    escale_kernel<<<NB, 1024>>>();
    rowmax_kernel<<<NB * NLQ / 8, 256>>>(mask);
    dim3 vg(NDV / 32, NLK / 32, NB);
    vt_kernel<<<vg, 256>>>(value);
    dim3 grid(NLQ / BM, NDV / BN, NB);
    attn_gemm<<<grid, 256, SMEM_REQ>>>(out);
}

// round 13
// speedup vs baseline: 1.2975x; 1.0650x over previous
#include <cuda_runtime.h>
#include <cuda_fp16.h>
#include <cstdint>
#include <cstddef>
#include <math.h>

#define NB  16
#define NLQ 1024
#define NLK 1024
#define NDK 256
#define NDV 256
#define EBIAS 44.3614195558365f

__device__ float    g_ks[NB * NLK];
__device__ unsigned g_maxi[NB];                    // zero-init; atomicMax idempotent
__device__ float    g_inv[NB * NLQ];               // exp(mx - rowmax(masked ks) - EBIAS)
__device__ unsigned g_bits[NB * NLQ * 32];         // word w bit 4i+c <-> k=i*128+w*4+c
__device__ __half   g_vt[(size_t)NB * NDV * NLK];

__device__ __forceinline__ unsigned enc_ord(float f) {
    int x = __float_as_int(f);
    return (x >= 0) ? ((unsigned)x | 0x80000000u) : ~(unsigned)x;
}
__device__ __forceinline__ float dec_ord(unsigned u) {
    int x = (u & 0x80000000u) ? (int)(u & 0x7fffffffu) : (int)~u;
    return __int_as_float(x);
}

// ---- 1) k_s = key·w, per-batch max ------------------------------------------
__global__ void ks_kernel(const float* __restrict__ key, const float* __restrict__ w) {
    __shared__ float ws[NDK];
    __shared__ float bm[8];
    int t = threadIdx.x;
    ws[t] = w[t];
    __syncthreads();
    int warp = t >> 5, lane = t & 31;
    int row = blockIdx.x * 8 + warp;
    const float4* kp = (const float4*)(key + (size_t)row * NDK);
    const float4* wp = (const float4*)ws;
    float s = 0.f;
#pragma unroll
    for (int i = 0; i < 2; i++) {
        float4 a = kp[lane + 32 * i], b4 = wp[lane + 32 * i];
        s = fmaf(a.x, b4.x, s); s = fmaf(a.y, b4.y, s);
        s = fmaf(a.z, b4.z, s); s = fmaf(a.w, b4.w, s);
    }
#pragma unroll
    for (int o = 16; o; o >>= 1) s += __shfl_xor_sync(0xffffffffu, s, o);
    if (lane == 0) { g_ks[row] = s; bm[warp] = s; }
    __syncthreads();
    if (t == 0) {
        float m = bm[0];
#pragma unroll
        for (int i = 1; i < 8; i++) m = fmaxf(m, bm[i]);
        atomicMax(&g_maxi[(unsigned)blockIdx.x >> 7], enc_ord(m));
    }
}

// ---- 2) per-row masked max over ks (monotone => no es needed) + bit-pack ----
__global__ void rowmax_kernel(const int* __restrict__ mask) {
    int wid = threadIdx.x >> 5, lane = threadIdx.x & 31;
    int row = blockIdx.x * 8 + wid;
    int b = row >> 10;
    const int4*   mp = (const int4*)(mask + (size_t)row * NLK);
    const float4* ep = (const float4*)(g_ks + b * NLK);
    float m = -1e30f;
    unsigned w = 0;
#pragma unroll
    for (int i = 0; i < 8; i++) {
        int idx = i * 32 + lane;            // k = idx*4 (coalesced)
        int4 mm = mp[idx];
        float4 ee = ep[idx];
        if (mm.x) m = fmaxf(m, ee.x);
        if (mm.y) m = fmaxf(m, ee.y);
        if (mm.z) m = fmaxf(m, ee.z);
        if (mm.w) m = fmaxf(m, ee.w);
        unsigned nib = (unsigned)(mm.x & 1) | ((unsigned)(mm.y & 1) << 1)
                     | ((unsigned)(mm.z & 1) << 2) | ((unsigned)(mm.w & 1) << 3);
        w |= nib << (4 * i);
    }
    g_bits[row * 32 + lane] = w;
#pragma unroll
    for (int o = 16; o; o >>= 1) m = fmaxf(m, __shfl_xor_sync(0xffffffffu, m, o));
    if (lane == 0) {
        float mx = dec_ord(g_maxi[b]);
        g_inv[row] = expf(mx - m - EBIAS);   // == 1 / es(rowmax)
    }
}

// ---- 3) V^T fp16 transpose --------------------------------------------------
__global__ void vt_kernel(const float* __restrict__ value) {
    __shared__ float tile[32][33];
    int b = blockIdx.z, k0 = blockIdx.y * 32, dv0 = blockIdx.x * 32;
    int t = threadIdx.x;
    int r = t >> 3, c4 = (t & 7) * 4;
    float4 v = *(const float4*)(value + ((size_t)(b * NLK + k0 + r)) * NDV + dv0 + c4);
    tile[r][c4 + 0] = v.x; tile[r][c4 + 1] = v.y;
    tile[r][c4 + 2] = v.z; tile[r][c4 + 3] = v.w;
    __syncthreads();
    __half2 h0 = __floats2half2_rn(tile[c4 + 0][r], tile[c4 + 1][r]);
    __half2 h1 = __floats2half2_rn(tile[c4 + 2][r], tile[c4 + 3][r]);
    uint2 o;
    o.x = *(unsigned*)&h0; o.y = *(unsigned*)&h1;
    *(uint2*)(g_vt + ((size_t)(b * NDV + dv0 + r)) * NLK + k0 + c4) = o;
}

// ---- 4) fp16 GEMM: BM=128 x BN=128, BK=64, 2 stages, 2 CTAs/SM --------------
#define BM 128
#define BN 128
#define BK 64
#define STG 2
#define APITCH 144
#define BPITCH 144
#define A_STAGE (BM * APITCH)              // 18432
#define B_STAGE (BN * BPITCH)              // 18432
#define OFF_B   (STG * A_STAGE)            // 36864
#define OFF_ES  (OFF_B + STG * B_STAGE)    // 73728
#define OFF_D   (OFF_ES + 4096)            // 77824
#define SMEM_REQ (OFF_D + 1024)            // 78848  (x2 CTAs = 157 KB/SM)

__device__ __forceinline__ void ldsm4(uint32_t* r, uint32_t addr) {
    asm volatile("ldmatrix.sync.aligned.m8n8.x4.shared.b16 {%0,%1,%2,%3}, [%4];"
                 : "=r"(r[0]), "=r"(r[1]), "=r"(r[2]), "=r"(r[3]) : "r"(addr));
}

__global__ __launch_bounds__(256, 2)
void attn_gemm(float* __restrict__ out) {
    extern __shared__ char smem[];
    const uint32_t sm = (uint32_t)__cvta_generic_to_shared(smem);
    float* Dens = (float*)(smem + OFF_D);

    const int tid = threadIdx.x, lane = tid & 31, wid = tid >> 5;
    const int b = blockIdx.z, qbase = blockIdx.x * BM, nbase = blockIdx.y * BN;
    const int warpM = wid >> 2, warpN = wid & 3;   // 2 x 4 warps, tile 64x32
    const int g = lane >> 2, t4 = lane & 3;

    {   // in-kernel es table: es[k] = exp(ks - mx + EBIAS), fp32, 4 KB
        float mx = dec_ord(g_maxi[b]);
        float4 k4 = ((const float4*)(g_ks + b * NLK))[tid];
        float4 e4;
        e4.x = expf(k4.x - mx + EBIAS); e4.y = expf(k4.y - mx + EBIAS);
        e4.z = expf(k4.z - mx + EBIAS); e4.w = expf(k4.w - mx + EBIAS);
        ((float4*)(smem + OFF_ES))[tid] = e4;
    }
    __syncthreads();

    const int ar = tid & 127, aq = tid >> 7;       // row, k-half (32 k each)
    const int grow = b * NLQ + qbase + ar;
    const float inv = g_inv[grow];
    // bit-words: even chunks use words 8aq..+7, odd chunks 16+8aq..+7
    unsigned wwe[8], wwo[8];
    {
        const uint4* bp = (const uint4*)(g_bits + (size_t)grow * 32);
        uint4 v0 = bp[2 * aq], v1 = bp[2 * aq + 1];
        uint4 v2 = bp[4 + 2 * aq], v3 = bp[5 + 2 * aq];
        wwe[0] = v0.x; wwe[1] = v0.y; wwe[2] = v0.z; wwe[3] = v0.w;
        wwe[4] = v1.x; wwe[5] = v1.y; wwe[6] = v1.z; wwe[7] = v1.w;
        wwo[0] = v2.x; wwo[1] = v2.y; wwo[2] = v2.z; wwo[3] = v2.w;
        wwo[4] = v3.x; wwo[5] = v3.y; wwo[6] = v3.z; wwo[7] = v3.w;
    }
    // B loader: 2 threads/row, 64B each
    const int brow_ = tid >> 1, bco = (tid & 1) * 32;    // halfs offset
    const __half* vb0 = g_vt + ((size_t)(b * NDV + nbase + brow_)) * NLK + bco;
    const uint32_t bd0 = sm + OFF_B + (uint32_t)(brow_ * BPITCH + bco * 2);

    float c[4][4][4];
#pragma unroll
    for (int i = 0; i < 4; i++)
#pragma unroll
        for (int j = 0; j < 4; j++)
#pragma unroll
            for (int k = 0; k < 4; k++) c[i][j][k] = 0.f;
    float dacc = 0.f;

    auto cpB = [&](int t, int s) {
        uint32_t dst = bd0 + (uint32_t)(s * B_STAGE);
        const __half* src = vb0 + t * BK;
        asm volatile("cp.async.cg.shared.global [%0], [%1], 16;" :: "r"(dst),      "l"(src));
        asm volatile("cp.async.cg.shared.global [%0], [%1], 16;" :: "r"(dst + 16), "l"(src + 8));
        asm volatile("cp.async.cg.shared.global [%0], [%1], 16;" :: "r"(dst + 32), "l"(src + 16));
        asm volatile("cp.async.cg.shared.global [%0], [%1], 16;" :: "r"(dst + 48), "l"(src + 24));
        asm volatile("cp.async.commit_group;" ::: "memory");
    };
    auto stsA = [&](int t, int s) {
        const unsigned* ww = (t & 1) ? wwo : wwe;
        const int sh = (t >> 1) * 4;
        const uint32_t ea = sm + OFF_ES + (uint32_t)(t * 256 + aq * 128);
        const uint32_t sa = sm + (uint32_t)(s * A_STAGE + ar * APITCH + aq * 64);
#pragma unroll
        for (int qp = 0; qp < 4; qp++) {        // 2 q per group -> one st.v4
            __half2 h[4];
#pragma unroll
            for (int h2i = 0; h2i < 2; h2i++) {
                const int q = qp * 2 + h2i;
                unsigned nb = (ww[q] >> sh) & 0xFu;
                float4 e;
                asm volatile("ld.shared.v4.f32 {%0,%1,%2,%3}, [%4];"
                             : "=f"(e.x), "=f"(e.y), "=f"(e.z), "=f"(e.w)
                             : "r"(ea + (uint32_t)(q * 16)));
                float a0 = (nb & 1u) ? e.x * inv : 0.f;
                float a1 = (nb & 2u) ? e.y * inv : 0.f;
                float a2 = (nb & 4u) ? e.z * inv : 0.f;
                float a3 = (nb & 8u) ? e.w * inv : 0.f;
                h[2 * h2i]     = __floats2half2_rn(a0, a1);
                h[2 * h2i + 1] = __floats2half2_rn(a2, a3);
                float2 f0 = __half22float2(h[2 * h2i]);
                float2 f1 = __half22float2(h[2 * h2i + 1]);
                dacc += (f0.x + f0.y) + (f1.x + f1.y);
            }
            asm volatile("st.shared.v4.b32 [%0], {%1,%2,%3,%4};"
                         :: "r"(sa + (uint32_t)(qp * 16)),
                            "r"(*(unsigned*)&h[0]), "r"(*(unsigned*)&h[1]),
                            "r"(*(unsigned*)&h[2]), "r"(*(unsigned*)&h[3]));
        }
    };
    auto compute = [&](int s) {
        const uint32_t Ab = sm + (uint32_t)(s * A_STAGE);
        const uint32_t Bb = sm + OFF_B + (uint32_t)(s * B_STAGE);
        const uint32_t aad = Ab + (uint32_t)((warpM * 64 + (lane & 15)) * APITCH
                                             + (lane >> 4) * 16);
        const uint32_t bad = Bb + (uint32_t)((warpN * 32 + (lane & 7) + (lane >> 4) * 8) * BPITCH
                                             + ((lane >> 3) & 1) * 16);
#pragma unroll
        for (int k16 = 0; k16 < 4; k16++) {
            uint32_t a[4][4], bq[2][4];
#pragma unroll
            for (int mt = 0; mt < 4; mt++)
                ldsm4(a[mt], aad + (uint32_t)(mt * 16 * APITCH + k16 * 32));
#pragma unroll
            for (int np = 0; np < 2; np++)
                ldsm4(bq[np], bad + (uint32_t)(np * 16 * BPITCH + k16 * 32));
#pragma unroll
            for (int mt = 0; mt < 4; mt++)
#pragma unroll
                for (int nt = 0; nt < 4; nt++) {
                    const uint32_t b0 = bq[nt >> 1][(nt & 1) * 2];
                    const uint32_t b1 = bq[nt >> 1][(nt & 1) * 2 + 1];
                    asm volatile(
                        "mma.sync.aligned.m16n8k16.row.col.f32.f16.f16.f32 "
                        "{%0,%1,%2,%3}, {%4,%5,%6,%7}, {%8,%9}, {%0,%1,%2,%3};"
                        : "+f"(c[mt][nt][0]), "+f"(c[mt][nt][1]),
                          "+f"(c[mt][nt][2]), "+f"(c[mt][nt][3])
                        : "r"(a[mt][0]), "r"(a[mt][1]), "r"(a[mt][2]), "r"(a[mt][3]),
                          "r"(b0), "r"(b1));
                }
        }
    };

    // ---- 2-stage pipeline, 16 iterations ----
    cpB(0, 0);
    const int NKT = NLK / BK;   // 16
    for (int t = 0; t < NKT; t++) {
        int cs = t & 1;
        stsA(t, cs);
        asm volatile("cp.async.wait_group 0;" ::: "memory");
        __syncthreads();
        if (t + 1 < NKT) cpB(t + 1, cs ^ 1);
        compute(cs);
    }

    // ---- denominators & epilogue ----
    Dens[ar * 2 + aq] = dacc;
    __syncthreads();
#pragma unroll
    for (int mt = 0; mt < 4; mt++) {
        const int row = warpM * 64 + mt * 16 + g;
        float2 d0 = *(const float2*)(Dens + row * 2);
        float2 d1 = *(const float2*)(Dens + (row + 8) * 2);
        float inv0 = 1.0f / (d0.x + d0.y);
        float inv8 = 1.0f / (d1.x + d1.y);
        float* o0 = out + ((size_t)(b * NLQ + qbase + row)) * NDV + nbase;
#pragma unroll
        for (int nt = 0; nt < 4; nt++) {
            const int col = warpN * 32 + nt * 8 + 2 * t4;
            *(float2*)(o0 + col) =
                make_float2(c[mt][nt][0] * inv0, c[mt][nt][1] * inv0);
            *(float2*)(o0 + 8 * NDV + col) =
                make_float2(c[mt][nt][2] * inv8, c[mt][nt][3] * inv8);
        }
    }
}

// ---------------- launcher --------------------------------------------------
extern "C" void kernel_launch(void* const* d_in, const int* in_sizes, int n_in,
                              void* d_out, int out_size) {
    const float* key   = (const float*)d_in[1];
    const float* value = (const float*)d_in[2];
    const float* w     = (const float*)d_in[3];
    const int*   mask  = (const int*)d_in[4];
    float*       out   = (float*)d_out;

    cudaFuncSetAttribute(attn_gemm,
                         cudaFuncAttributeMaxDynamicSharedMemorySize, SMEM_REQ);

    ks_kernel<<<NB * NLK / 8, 256>>>(key, w);
    rowmax_kernel<<<NB * NLQ / 8, 256>>>(mask);
    dim3 vg(NDV / 32, NLK / 32, NB);
    vt_kernel<<<vg, 256>>>(value);
    dim3 grid(NLQ / BM, NDV / BN, NB);
    attn_gemm<<<grid, 256, SMEM_REQ>>>(out);
}

// round 14
// speedup vs baseline: 1.3615x; 1.0494x over previous
#include <cuda_runtime.h>
#include <cuda_fp16.h>
#include <cstdint>
#include <cstddef>
#include <math.h>

#define NB  16
#define NLQ 1024
#define NLK 1024
#define NDK 256
#define NDV 256
#define EBIAS 44.3614195558365f

__device__ float    g_ks[NB * NLK];
__device__ unsigned g_maxi[NB];                    // zero-init; atomicMax idempotent
__device__ float    g_inv[NB * NLQ];
__device__ unsigned g_bits[NB * NLQ * 32];         // word w bit 4i+c <-> k=i*128+w*4+c
__device__ __half   g_vt[(size_t)NB * NDV * NLK];

__device__ __forceinline__ unsigned enc_ord(float f) {
    int x = __float_as_int(f);
    return (x >= 0) ? ((unsigned)x | 0x80000000u) : ~(unsigned)x;
}
__device__ __forceinline__ float dec_ord(unsigned u) {
    int x = (u & 0x80000000u) ? (int)(u & 0x7fffffffu) : (int)~u;
    return __int_as_float(x);
}

// ---- 1) fused prep: ks (blocks 0..2047) + V^T transpose (blocks 2048..6143) -
__global__ void prep_kernel(const float* __restrict__ key, const float* __restrict__ w,
                            const float* __restrict__ value) {
    __shared__ float sbuf[32][33];                 // union: vt tile / ks ws+bm
    int t = threadIdx.x;
    if (blockIdx.x < 2048) {
        float* ws = &sbuf[0][0];                   // 256 floats
        float* bm = &sbuf[31][0];                  // 8 floats (disjoint: 256 <= 31*33)
        ws[t] = w[t];
        __syncthreads();
        int warp = t >> 5, lane = t & 31;
        int row = blockIdx.x * 8 + warp;
        const float4* kp = (const float4*)(key + (size_t)row * NDK);
        const float4* wp = (const float4*)ws;
        float s = 0.f;
#pragma unroll
        for (int i = 0; i < 2; i++) {
            float4 a = kp[lane + 32 * i], b4 = wp[lane + 32 * i];
            s = fmaf(a.x, b4.x, s); s = fmaf(a.y, b4.y, s);
            s = fmaf(a.z, b4.z, s); s = fmaf(a.w, b4.w, s);
        }
#pragma unroll
        for (int o = 16; o; o >>= 1) s += __shfl_xor_sync(0xffffffffu, s, o);
        if (lane == 0) { g_ks[row] = s; bm[warp] = s; }
        __syncthreads();
        if (t == 0) {
            float m = bm[0];
#pragma unroll
            for (int i = 1; i < 8; i++) m = fmaxf(m, bm[i]);
            atomicMax(&g_maxi[(unsigned)blockIdx.x >> 7], enc_ord(m));
        }
    } else {
        int bid = blockIdx.x - 2048;
        int dv0 = (bid & 7) * 32, k0 = ((bid >> 3) & 31) * 32, b = bid >> 8;
        int r = t >> 3, c4 = (t & 7) * 4;
        float4 v = *(const float4*)(value + ((size_t)(b * NLK + k0 + r)) * NDV + dv0 + c4);
        sbuf[r][c4 + 0] = v.x; sbuf[r][c4 + 1] = v.y;
        sbuf[r][c4 + 2] = v.z; sbuf[r][c4 + 3] = v.w;
        __syncthreads();
        __half2 h0 = __floats2half2_rn(sbuf[c4 + 0][r], sbuf[c4 + 1][r]);
        __half2 h1 = __floats2half2_rn(sbuf[c4 + 2][r], sbuf[c4 + 3][r]);
        uint2 o;
        o.x = *(unsigned*)&h0; o.y = *(unsigned*)&h1;
        *(uint2*)(g_vt + ((size_t)(b * NDV + dv0 + r)) * NLK + k0 + c4) = o;
    }
}

// ---- 2) per-row masked max over ks + bit-pack -------------------------------
__global__ void rowmax_kernel(const int* __restrict__ mask) {
    int wid = threadIdx.x >> 5, lane = threadIdx.x & 31;
    int row = blockIdx.x * 8 + wid;
    int b = row >> 10;
    const int4*   mp = (const int4*)(mask + (size_t)row * NLK);
    const float4* ep = (const float4*)(g_ks + b * NLK);
    float m = -1e30f;
    unsigned w = 0;
#pragma unroll
    for (int i = 0; i < 8; i++) {
        int idx = i * 32 + lane;
        int4 mm = mp[idx];
        float4 ee = ep[idx];
        if (mm.x) m = fmaxf(m, ee.x);
        if (mm.y) m = fmaxf(m, ee.y);
        if (mm.z) m = fmaxf(m, ee.z);
        if (mm.w) m = fmaxf(m, ee.w);
        unsigned nib = (unsigned)(mm.x & 1) | ((unsigned)(mm.y & 1) << 1)
                     | ((unsigned)(mm.z & 1) << 2) | ((unsigned)(mm.w & 1) << 3);
        w |= nib << (4 * i);
    }
    g_bits[row * 32 + lane] = w;
#pragma unroll
    for (int o = 16; o; o >>= 1) m = fmaxf(m, __shfl_xor_sync(0xffffffffu, m, o));
    if (lane == 0) {
        float mx = dec_ord(g_maxi[b]);
        g_inv[row] = expf(mx - m - EBIAS);
    }
}

// ---- 3) fp16 GEMM: BK=64, A double-buffered + pipelined conversion ---------
#define BM 128
#define BN 128
#define BK 64
#define APITCH 144
#define BPITCH 144
#define A_STAGE (BM * APITCH)              // 18432
#define B_STAGE (BN * BPITCH)              // 18432
#define OFF_B   (2 * A_STAGE)              // 36864  (A: 2 stages)
#define OFF_ES  (OFF_B + 3 * B_STAGE)      // 92160  (B: 3 stages)
#define OFF_D   (OFF_ES + 4096)            // 96256
#define SMEM_REQ (OFF_D + 1024)            // 97280  (x2 CTAs = 195 KB/SM)

__device__ __forceinline__ void ldsm4(uint32_t* r, uint32_t addr) {
    asm volatile("ldmatrix.sync.aligned.m8n8.x4.shared.b16 {%0,%1,%2,%3}, [%4];"
                 : "=r"(r[0]), "=r"(r[1]), "=r"(r[2]), "=r"(r[3]) : "r"(addr));
}

__global__ __launch_bounds__(256, 2)
void attn_gemm(float* __restrict__ out) {
    extern __shared__ char smem[];
    const uint32_t sm = (uint32_t)__cvta_generic_to_shared(smem);
    float* Dens = (float*)(smem + OFF_D);

    const int tid = threadIdx.x, lane = tid & 31, wid = tid >> 5;
    const int b = blockIdx.z, qbase = blockIdx.x * BM, nbase = blockIdx.y * BN;
    const int warpM = wid >> 2, warpN = wid & 3;   // 2 x 4 warps, tile 64x32
    const int g = lane >> 2, t4 = lane & 3;

    {   // in-kernel es table (fp32, 4 KB)
        float mx = dec_ord(g_maxi[b]);
        float4 k4 = ((const float4*)(g_ks + b * NLK))[tid];
        float4 e4;
        e4.x = expf(k4.x - mx + EBIAS); e4.y = expf(k4.y - mx + EBIAS);
        e4.z = expf(k4.z - mx + EBIAS); e4.w = expf(k4.w - mx + EBIAS);
        ((float4*)(smem + OFF_ES))[tid] = e4;
    }
    __syncthreads();

    const int ar = tid & 127, aq = tid >> 7;       // row, k-half (32 k each)
    const int grow = b * NLQ + qbase + ar;
    const float inv = g_inv[grow];
    unsigned wwe[8], wwo[8];
    {
        const uint4* bp = (const uint4*)(g_bits + (size_t)grow * 32);
        uint4 v0 = bp[2 * aq], v1 = bp[2 * aq + 1];
        uint4 v2 = bp[4 + 2 * aq], v3 = bp[5 + 2 * aq];
        wwe[0] = v0.x; wwe[1] = v0.y; wwe[2] = v0.z; wwe[3] = v0.w;
        wwe[4] = v1.x; wwe[5] = v1.y; wwe[6] = v1.z; wwe[7] = v1.w;
        wwo[0] = v2.x; wwo[1] = v2.y; wwo[2] = v2.z; wwo[3] = v2.w;
        wwo[4] = v3.x; wwo[5] = v3.y; wwo[6] = v3.z; wwo[7] = v3.w;
    }
    const int brow_ = tid >> 1, bco = (tid & 1) * 32;
    const __half* vb0 = g_vt + ((size_t)(b * NDV + nbase + brow_)) * NLK + bco;
    const uint32_t bd0 = sm + OFF_B + (uint32_t)(brow_ * BPITCH + bco * 2);

    float c[4][4][4];
#pragma unroll
    for (int i = 0; i < 4; i++)
#pragma unroll
        for (int j = 0; j < 4; j++)
#pragma unroll
            for (int k = 0; k < 4; k++) c[i][j][k] = 0.f;
    float dacc = 0.f;

    auto cpB = [&](int t, int s) {
        uint32_t dst = bd0 + (uint32_t)(s * B_STAGE);
        const __half* src = vb0 + t * BK;
        asm volatile("cp.async.cg.shared.global [%0], [%1], 16;" :: "r"(dst),      "l"(src));
        asm volatile("cp.async.cg.shared.global [%0], [%1], 16;" :: "r"(dst + 16), "l"(src + 8));
        asm volatile("cp.async.cg.shared.global [%0], [%1], 16;" :: "r"(dst + 32), "l"(src + 16));
        asm volatile("cp.async.cg.shared.global [%0], [%1], 16;" :: "r"(dst + 48), "l"(src + 24));
        asm volatile("cp.async.commit_group;" ::: "memory");
    };
    auto stsA = [&](int t, int s) {
        const unsigned* ww = (t & 1) ? wwo : wwe;
        const int sh = (t >> 1) * 4;
        const uint32_t ea = sm + OFF_ES + (uint32_t)(t * 256 + aq * 128);
        const uint32_t sa = sm + (uint32_t)(s * A_STAGE + ar * APITCH + aq * 64);
#pragma unroll
        for (int qp = 0; qp < 4; qp++) {
            __half2 h[4];
#pragma unroll
            for (int h2i = 0; h2i < 2; h2i++) {
                const int q = qp * 2 + h2i;
                unsigned nb = (ww[q] >> sh) & 0xFu;
                float4 e;
                asm volatile("ld.shared.v4.f32 {%0,%1,%2,%3}, [%4];"
                             : "=f"(e.x), "=f"(e.y), "=f"(e.z), "=f"(e.w)
                             : "r"(ea + (uint32_t)(q * 16)));
                float a0 = (nb & 1u) ? e.x * inv : 0.f;
                float a1 = (nb & 2u) ? e.y * inv : 0.f;
                float a2 = (nb & 4u) ? e.z * inv : 0.f;
                float a3 = (nb & 8u) ? e.w * inv : 0.f;
                h[2 * h2i]     = __floats2half2_rn(a0, a1);
                h[2 * h2i + 1] = __floats2half2_rn(a2, a3);
                float2 f0 = __half22float2(h[2 * h2i]);
                float2 f1 = __half22float2(h[2 * h2i + 1]);
                dacc += (f0.x + f0.y) + (f1.x + f1.y);
            }
            asm volatile("st.shared.v4.b32 [%0], {%1,%2,%3,%4};"
                         :: "r"(sa + (uint32_t)(qp * 16)),
                            "r"(*(unsigned*)&h[0]), "r"(*(unsigned*)&h[1]),
                            "r"(*(unsigned*)&h[2]), "r"(*(unsigned*)&h[3]));
        }
    };
    auto compute = [&](int as, int bs) {
        const uint32_t Ab = sm + (uint32_t)(as * A_STAGE);
        const uint32_t Bb = sm + OFF_B + (uint32_t)(bs * B_STAGE);
        const uint32_t aad = Ab + (uint32_t)((warpM * 64 + (lane & 15)) * APITCH
                                             + (lane >> 4) * 16);
        const uint32_t bad = Bb + (uint32_t)((warpN * 32 + (lane & 7) + (lane >> 4) * 8) * BPITCH
                                             + ((lane >> 3) & 1) * 16);
#pragma unroll
        for (int k16 = 0; k16 < 4; k16++) {
            uint32_t a[4][4], bq[2][4];
#pragma unroll
            for (int mt = 0; mt < 4; mt++)
                ldsm4(a[mt], aad + (uint32_t)(mt * 16 * APITCH + k16 * 32));
#pragma unroll
            for (int np = 0; np < 2; np++)
                ldsm4(bq[np], bad + (uint32_t)(np * 16 * BPITCH + k16 * 32));
#pragma unroll
            for (int mt = 0; mt < 4; mt++)
#pragma unroll
                for (int nt = 0; nt < 4; nt++) {
                    const uint32_t b0 = bq[nt >> 1][(nt & 1) * 2];
                    const uint32_t b1 = bq[nt >> 1][(nt & 1) * 2 + 1];
                    asm volatile(
                        "mma.sync.aligned.m16n8k16.row.col.f32.f16.f16.f32 "
                        "{%0,%1,%2,%3}, {%4,%5,%6,%7}, {%8,%9}, {%0,%1,%2,%3};"
                        : "+f"(c[mt][nt][0]), "+f"(c[mt][nt][1]),
                          "+f"(c[mt][nt][2]), "+f"(c[mt][nt][3])
                        : "r"(a[mt][0]), "r"(a[mt][1]), "r"(a[mt][2]), "r"(a[mt][3]),
                          "r"(b0), "r"(b1));
                }
        }
    };

    // ---- pipeline: A converted one iteration ahead; B 3-stage, depth-2 -----
    stsA(0, 0);
    cpB(0, 0);
    cpB(1, 1);
    const int NKT = NLK / BK;   // 16
#pragma unroll 1
    for (int t = 0; t < NKT; t++) {
        const int as = t & 1, bs = t % 3;
        if (t < NKT - 1) asm volatile("cp.async.wait_group 1;" ::: "memory");
        else             asm volatile("cp.async.wait_group 0;" ::: "memory");
        __syncthreads();                       // A(t), B(t) published
        if (t + 2 < NKT) cpB(t + 2, (t + 2) % 3);
        compute(as, bs);
        if (t + 1 < NKT) stsA(t + 1, as ^ 1);  // overlapped with next wait
    }

    // ---- denominators & epilogue ----
    Dens[ar * 2 + aq] = dacc;
    __syncthreads();
#pragma unroll
    for (int mt = 0; mt < 4; mt++) {
        const int row = warpM * 64 + mt * 16 + g;
        float2 d0 = *(const float2*)(Dens + row * 2);
        float2 d1 = *(const float2*)(Dens + (row + 8) * 2);
        float inv0 = 1.0f / (d0.x + d0.y);
        float inv8 = 1.0f / (d1.x + d1.y);
        float* o0 = out + ((size_t)(b * NLQ + qbase + row)) * NDV + nbase;
#pragma unroll
        for (int nt = 0; nt < 4; nt++) {
            const int col = warpN * 32 + nt * 8 + 2 * t4;
            *(float2*)(o0 + col) =
                make_float2(c[mt][nt][0] * inv0, c[mt][nt][1] * inv0);
            *(float2*)(o0 + 8 * NDV + col) =
                make_float2(c[mt][nt][2] * inv8, c[mt][nt][3] * inv8);
        }
    }
}

// ---------------- launcher --------------------------------------------------
extern "C" void kernel_launch(void* const* d_in, const int* in_sizes, int n_in,
                              void* d_out, int out_size) {
    const float* key   = (const float*)d_in[1];
    const float* value = (const float*)d_in[2];
    const float* w     = (const float*)d_in[3];
    const int*   mask  = (const int*)d_in[4];
    float*       out   = (float*)d_out;

    cudaFuncSetAttribute(attn_gemm,
                         cudaFuncAttributeMaxDynamicSharedMemorySize, SMEM_REQ);

    prep_kernel<<<2048 + NB * NLK / 32 * (NDV / 32) / 1, 256>>>(key, w, value);
    rowmax_kernel<<<NB * NLQ / 8, 256>>>(mask);
    dim3 grid(NLQ / BM, NDV / BN, NB);
    attn_gemm<<<grid, 256, SMEM_REQ>>>(out);
}